// round 1
// baseline (speedup 1.0000x reference)
#include <cuda_runtime.h>
#include <math.h>

// ---------------- problem constants ----------------
#define Bn   4
#define Sd   4096
#define Dd   1024
#define Hh   8
#define Ee   128
#define Ff   4096          // EXP * D
#define Mtok 16384         // B * S
#define NCH  64            // scan chunks
#define CH   (Sd / NCH)    // 64 steps per chunk

// ---------------- scratch (device globals; no allocations allowed) ----------
__device__ float g_hln  [(size_t)Mtok * Dd];   // 64 MB
__device__ float g_act  [(size_t)Mtok * Ff];   // 256 MB
__device__ float g_x2   [(size_t)Mtok * Dd];   // 64 MB
__device__ float g_h2   [(size_t)Mtok * Dd];   // 64 MB
__device__ float g_p    [(size_t)Mtok * Dd];   // 64 MB
__device__ float g_mixed[(size_t)Mtok * Dd];   // 64 MB
__device__ float g_carry[(size_t)Bn * NCH * Dd];

// ---------------- LayerNorm: one block per token row (D=1024) ---------------
__global__ void __launch_bounds__(256) ln_kernel(
    const float* __restrict__ x, const float* __restrict__ g,
    const float* __restrict__ bet, float* __restrict__ out)
{
    __shared__ float red[64];
    const long row = blockIdx.x;
    const int  t   = threadIdx.x;

    float4 v = ((const float4*)(x + row * Dd))[t];
    float s = v.x + v.y + v.z + v.w;
    float q = fmaf(v.x, v.x, fmaf(v.y, v.y, fmaf(v.z, v.z, v.w * v.w)));

    #pragma unroll
    for (int o = 16; o > 0; o >>= 1) {
        s += __shfl_xor_sync(0xffffffffu, s, o);
        q += __shfl_xor_sync(0xffffffffu, q, o);
    }
    if ((t & 31) == 0) { red[t >> 5] = s; red[32 + (t >> 5)] = q; }
    __syncthreads();
    if (t < 32) {
        s = (t < 8) ? red[t]      : 0.f;
        q = (t < 8) ? red[32 + t] : 0.f;
        #pragma unroll
        for (int o = 4; o > 0; o >>= 1) {
            s += __shfl_xor_sync(0xffffffffu, s, o);
            q += __shfl_xor_sync(0xffffffffu, q, o);
        }
        if (t == 0) { red[0] = s; red[1] = q; }
    }
    __syncthreads();

    const float mean = red[0] * (1.f / Dd);
    const float var  = red[1] * (1.f / Dd) - mean * mean;
    const float rstd = rsqrtf(var + 1e-5f);

    float4 gg = ((const float4*)g)[t];
    float4 bb = ((const float4*)bet)[t];
    float4 o;
    o.x = (v.x - mean) * rstd * gg.x + bb.x;
    o.y = (v.y - mean) * rstd * gg.y + bb.y;
    o.z = (v.z - mean) * rstd * gg.z + bb.z;
    o.w = (v.w - mean) * rstd * gg.w + bb.w;
    ((float4*)(out + row * Dd))[t] = o;
}

// ---------------- fp32 NT GEMM: C[M,N] = A[M,K] * W[N,K]^T + epilogue -------
// EPI: 0 = +bias, 1 = silu(+bias), 2 = +bias + residual
template <int EPI>
__global__ void __launch_bounds__(256, 2) gemm_nt(
    const float* __restrict__ A, const float* __restrict__ W,
    float* __restrict__ C, const float* __restrict__ bias,
    const float* __restrict__ resid, int M, int N, int K)
{
    __shared__ float As[2][16][132];
    __shared__ float Bs[2][16][132];

    const int tid = threadIdx.x;
    const int m0  = blockIdx.y * 128;
    const int n0  = blockIdx.x * 128;

    // global-load mapping: each thread loads rows (lr, lr+64), k cols [lc4, lc4+4)
    const int lr  = tid >> 2;          // 0..63
    const int lc4 = (tid & 3) * 4;     // 0,4,8,12

    const float* Aptr = A + (long)(m0 + lr) * K + lc4;
    const float* Wptr = W + (long)(n0 + lr) * K + lc4;
    const long   rstep = (long)64 * K;

    // compute mapping: 8x8 microtile
    const int rc = (tid >> 4) * 8;     // tile row base
    const int cc = (tid & 15) * 8;     // tile col base

    float acc[8][8];
    #pragma unroll
    for (int i = 0; i < 8; i++)
        #pragma unroll
        for (int j = 0; j < 8; j++) acc[i][j] = 0.f;

    // prologue: tile 0
    {
        float4 a0 = *(const float4*)(Aptr);
        float4 a1 = *(const float4*)(Aptr + rstep);
        float4 b0 = *(const float4*)(Wptr);
        float4 b1 = *(const float4*)(Wptr + rstep);
        As[0][lc4 + 0][lr] = a0.x; As[0][lc4 + 1][lr] = a0.y;
        As[0][lc4 + 2][lr] = a0.z; As[0][lc4 + 3][lr] = a0.w;
        As[0][lc4 + 0][lr + 64] = a1.x; As[0][lc4 + 1][lr + 64] = a1.y;
        As[0][lc4 + 2][lr + 64] = a1.z; As[0][lc4 + 3][lr + 64] = a1.w;
        Bs[0][lc4 + 0][lr] = b0.x; Bs[0][lc4 + 1][lr] = b0.y;
        Bs[0][lc4 + 2][lr] = b0.z; Bs[0][lc4 + 3][lr] = b0.w;
        Bs[0][lc4 + 0][lr + 64] = b1.x; Bs[0][lc4 + 1][lr + 64] = b1.y;
        Bs[0][lc4 + 2][lr + 64] = b1.z; Bs[0][lc4 + 3][lr + 64] = b1.w;
    }
    __syncthreads();

    const int nk = K / 16;
    int buf = 0;
    for (int kt = 0; kt < nk; kt++) {
        float4 na0, na1, nb0, nb1;
        const bool more = (kt + 1 < nk);
        if (more) {
            const float* Ap = Aptr + (kt + 1) * 16;
            const float* Wp = Wptr + (kt + 1) * 16;
            na0 = *(const float4*)(Ap);
            na1 = *(const float4*)(Ap + rstep);
            nb0 = *(const float4*)(Wp);
            nb1 = *(const float4*)(Wp + rstep);
        }

        #pragma unroll
        for (int kk = 0; kk < 16; kk++) {
            float4 t0 = *(const float4*)&As[buf][kk][rc];
            float4 t1 = *(const float4*)&As[buf][kk][rc + 4];
            float4 t2 = *(const float4*)&Bs[buf][kk][cc];
            float4 t3 = *(const float4*)&Bs[buf][kk][cc + 4];
            float a[8] = {t0.x, t0.y, t0.z, t0.w, t1.x, t1.y, t1.z, t1.w};
            float b[8] = {t2.x, t2.y, t2.z, t2.w, t3.x, t3.y, t3.z, t3.w};
            #pragma unroll
            for (int i = 0; i < 8; i++)
                #pragma unroll
                for (int j = 0; j < 8; j++)
                    acc[i][j] = fmaf(a[i], b[j], acc[i][j]);
        }

        if (more) {
            const int nb = buf ^ 1;
            As[nb][lc4 + 0][lr] = na0.x; As[nb][lc4 + 1][lr] = na0.y;
            As[nb][lc4 + 2][lr] = na0.z; As[nb][lc4 + 3][lr] = na0.w;
            As[nb][lc4 + 0][lr + 64] = na1.x; As[nb][lc4 + 1][lr + 64] = na1.y;
            As[nb][lc4 + 2][lr + 64] = na1.z; As[nb][lc4 + 3][lr + 64] = na1.w;
            Bs[nb][lc4 + 0][lr] = nb0.x; Bs[nb][lc4 + 1][lr] = nb0.y;
            Bs[nb][lc4 + 2][lr] = nb0.z; Bs[nb][lc4 + 3][lr] = nb0.w;
            Bs[nb][lc4 + 0][lr + 64] = nb1.x; Bs[nb][lc4 + 1][lr + 64] = nb1.y;
            Bs[nb][lc4 + 2][lr + 64] = nb1.z; Bs[nb][lc4 + 3][lr + 64] = nb1.w;
        }
        __syncthreads();
        buf ^= 1;
    }

    // epilogue
    float br[8];
    {
        float4 bb0 = *(const float4*)&bias[n0 + cc];
        float4 bb1 = *(const float4*)&bias[n0 + cc + 4];
        br[0] = bb0.x; br[1] = bb0.y; br[2] = bb0.z; br[3] = bb0.w;
        br[4] = bb1.x; br[5] = bb1.y; br[6] = bb1.z; br[7] = bb1.w;
    }
    #pragma unroll
    for (int i = 0; i < 8; i++) {
        const long row = m0 + rc + i;
        float v[8];
        #pragma unroll
        for (int j = 0; j < 8; j++) v[j] = acc[i][j] + br[j];
        if (EPI == 1) {
            #pragma unroll
            for (int j = 0; j < 8; j++) v[j] = v[j] / (1.f + expf(-v[j]));
        }
        if (EPI == 2) {
            float4 r0 = *(const float4*)&resid[row * N + n0 + cc];
            float4 r1 = *(const float4*)&resid[row * N + n0 + cc + 4];
            v[0] += r0.x; v[1] += r0.y; v[2] += r0.z; v[3] += r0.w;
            v[4] += r1.x; v[5] += r1.y; v[6] += r1.z; v[7] += r1.w;
        }
        float4 o0 = {v[0], v[1], v[2], v[3]};
        float4 o1 = {v[4], v[5], v[6], v[7]};
        *(float4*)&C[row * N + n0 + cc]     = o0;
        *(float4*)&C[row * N + n0 + cc + 4] = o1;
    }
}

// ---------------- decayed scan (3-pass chunked linear recurrence) -----------
__device__ __forceinline__ float head_decay(const float* dr_ptr, int h) {
    float dr = dr_ptr[h];
    dr = fminf(fmaxf(dr, 0.9f), 1.0f);
    return powf(dr, 0.125f);            // 1/DC, DC = 8
}

__global__ void __launch_bounds__(256) scan_pass1(
    const float* __restrict__ p, const float* __restrict__ mix_w,
    const float* __restrict__ decay_raw, float* __restrict__ carry)
{
    const int blk = blockIdx.x;          // Bn * NCH blocks
    const int b = blk / NCH, ch = blk % NCH;
    const int t = threadIdx.x;
    const int s0 = ch * CH;

    float cache[4] = {0.f, 0.f, 0.f, 0.f};
    float dly[4];
    #pragma unroll
    for (int j = 0; j < 4; j++) dly[j] = head_decay(decay_raw, (t + j * 256) >> 7);

    for (int s = s0; s < s0 + CH; s++) {
        const float* pr = p + ((long)b * Sd + s) * Dd;
        #pragma unroll
        for (int j = 0; j < 4; j++) {
            const int f = t + j * 256;
            const int h = f >> 7;
            const float c1 = (h < Hh / 2) ? 1.0f : mix_w[h * Sd + s];
            const float u  = pr[f] * c1;
            cache[j] = fmaf(dly[j], cache[j], u);
        }
    }
    #pragma unroll
    for (int j = 0; j < 4; j++)
        carry[((long)b * NCH + ch) * Dd + t + j * 256] = cache[j];
}

__global__ void __launch_bounds__(256) scan_pass2(
    const float* __restrict__ decay_raw, float* __restrict__ carry)
{
    const int idx = blockIdx.x * 256 + threadIdx.x;   // Bn * Dd threads
    const int b = idx >> 10, f = idx & 1023;
    const int h = f >> 7;
    float dr = fminf(fmaxf(decay_raw[h], 0.9f), 1.0f);
    float d2 = dr * dr;
    float d4 = d2 * d2;
    const float dC = d4 * d4;            // d^CH = (dr^(1/8))^64 = dr^8

    float cin = 0.f;
    for (int ch = 0; ch < NCH; ch++) {
        const long i = ((long)b * NCH + ch) * Dd + f;
        const float e = carry[i];
        carry[i] = cin;                  // carry-in for re-scan of chunk ch
        cin = fmaf(dC, cin, e);
    }
}

__global__ void __launch_bounds__(256) scan_pass3(
    const float* __restrict__ p, const float* __restrict__ mix_w,
    const float* __restrict__ mix_b, const float* __restrict__ decay_raw,
    const float* __restrict__ carry, float* __restrict__ mixed)
{
    const int blk = blockIdx.x;
    const int b = blk / NCH, ch = blk % NCH;
    const int t = threadIdx.x;
    const int s0 = ch * CH;

    float cache[4], dly[4];
    #pragma unroll
    for (int j = 0; j < 4; j++) {
        const int f = t + j * 256;
        dly[j]   = head_decay(decay_raw, f >> 7);
        cache[j] = carry[((long)b * NCH + ch) * Dd + f];
    }

    for (int s = s0; s < s0 + CH; s++) {
        const float* pr = p     + ((long)b * Sd + s) * Dd;
        float*       mr = mixed + ((long)b * Sd + s) * Dd;
        #pragma unroll
        for (int j = 0; j < 4; j++) {
            const int f = t + j * 256;
            const int h = f >> 7;
            const float mw = mix_w[h * Sd + s];
            const float c1 = (h < Hh / 2) ? 1.0f : mw;
            const float c2 = (h < Hh / 2) ? mw : 1.0f;
            const float u  = pr[f] * c1;
            cache[j] = fmaf(dly[j], cache[j], u);
            mr[f] = fmaf(c2, cache[j], mix_b[h * Sd + s]);
        }
    }
}

// ---------------- launcher ---------------------------------------------------
extern "C" void kernel_launch(void* const* d_in, const int* in_sizes, int n_in,
                              void* d_out, int out_size)
{
    const float* x         = (const float*)d_in[0];
    const float* ln1_g     = (const float*)d_in[1];
    const float* ln1_b     = (const float*)d_in[2];
    const float* w1        = (const float*)d_in[3];
    const float* b1        = (const float*)d_in[4];
    const float* w2        = (const float*)d_in[5];
    const float* b2        = (const float*)d_in[6];
    const float* ln2_g     = (const float*)d_in[7];
    const float* ln2_b     = (const float*)d_in[8];
    const float* proj_w    = (const float*)d_in[9];
    const float* proj_b    = (const float*)d_in[10];
    const float* mix_w     = (const float*)d_in[11];
    const float* mix_b     = (const float*)d_in[12];
    const float* decay_raw = (const float*)d_in[13];
    const float* out_w     = (const float*)d_in[14];
    const float* out_b     = (const float*)d_in[15];
    float* out = (float*)d_out;

    float *hln, *act, *x2, *h2, *pb, *mixed, *carry;
    cudaGetSymbolAddress((void**)&hln,   g_hln);
    cudaGetSymbolAddress((void**)&act,   g_act);
    cudaGetSymbolAddress((void**)&x2,    g_x2);
    cudaGetSymbolAddress((void**)&h2,    g_h2);
    cudaGetSymbolAddress((void**)&pb,    g_p);
    cudaGetSymbolAddress((void**)&mixed, g_mixed);
    cudaGetSymbolAddress((void**)&carry, g_carry);

    // 1) LN1
    ln_kernel<<<Mtok, 256>>>(x, ln1_g, ln1_b, hln);
    // 2) MLP up + SiLU  : act = silu(hln @ w1^T + b1)       [16384, 4096]
    gemm_nt<1><<<dim3(Ff / 128, Mtok / 128), 256>>>(hln, w1, act, b1, nullptr, Mtok, Ff, Dd);
    // 3) MLP down + res : x2 = act @ w2^T + b2 + x          [16384, 1024]
    gemm_nt<2><<<dim3(Dd / 128, Mtok / 128), 256>>>(act, w2, x2, b2, x, Mtok, Dd, Ff);
    // 4) LN2
    ln_kernel<<<Mtok, 256>>>(x2, ln2_g, ln2_b, h2);
    // 5) head projection: p = h2 @ proj_w^T + proj_b        [16384, 1024]
    gemm_nt<0><<<dim3(Dd / 128, Mtok / 128), 256>>>(h2, proj_w, pb, proj_b, nullptr, Mtok, Dd, Dd);
    // 6-8) decayed scan over S (chunked 3-pass)
    scan_pass1<<<Bn * NCH, 256>>>(pb, mix_w, decay_raw, carry);
    scan_pass2<<<(Bn * Dd) / 256, 256>>>(decay_raw, carry);
    scan_pass3<<<Bn * NCH, 256>>>(pb, mix_w, mix_b, decay_raw, carry, mixed);
    // 9) out projection + residual: out = mixed @ out_w^T + out_b + x2
    gemm_nt<2><<<dim3(Dd / 128, Mtok / 128), 256>>>(mixed, out_w, out, out_b, x2, Mtok, Dd, Dd);
}

// round 3
// speedup vs baseline: 2.2521x; 2.2521x over previous
#include <cuda_runtime.h>
#include <cuda_bf16.h>
#include <math.h>
#include <stdint.h>

// ---------------- problem constants ----------------
#define Bn   4
#define Sd   4096
#define Dd   1024
#define Hh   8
#define Ff   4096          // EXP * D
#define Mtok 16384         // B * S
#define NCH  64            // scan chunks
#define CH   (Sd / NCH)    // 64 steps per chunk

// GEMM tiling
#define BM 128
#define BN 128
#define BK 32
#define STAGES 4
#define STAGE_BYTES 32768          // Ah 8K | Al 8K | Bh 8K | Bl 8K
#define OFF_AH 0
#define OFF_AL 8192
#define OFF_BH 16384
#define OFF_BL 24576
#define GEMM_SMEM (STAGES * STAGE_BYTES)

// ---------------- small PTX helpers ------------------------------------------
__device__ __forceinline__ uint32_t smem_u32(const void* p) {
    uint32_t a;
    asm("{ .reg .u64 t; cvta.to.shared.u64 t, %1; cvt.u32.u64 %0, t; }"
        : "=r"(a) : "l"(p));
    return a;
}
#define CP_ASYNC16(dst, src) \
    asm volatile("cp.async.cg.shared.global [%0], [%1], 16;" \
        :: "r"(dst), "l"(src) : "memory")
#define CP_COMMIT() asm volatile("cp.async.commit_group;" ::: "memory")
#define CP_WAIT2()  asm volatile("cp.async.wait_group 2;" ::: "memory")

#define LDSM_X4(r0, r1, r2, r3, addr) \
    asm volatile("ldmatrix.sync.aligned.m8n8.x4.shared.b16 {%0,%1,%2,%3}, [%4];" \
        : "=r"(r0), "=r"(r1), "=r"(r2), "=r"(r3) : "r"(addr))

#define MMA_BF16(d, a, b) \
    asm volatile("mma.sync.aligned.m16n8k16.row.col.f32.bf16.bf16.f32 " \
        "{%0,%1,%2,%3}, {%4,%5,%6,%7}, {%8,%9}, {%0,%1,%2,%3};" \
        : "+f"((d)[0]), "+f"((d)[1]), "+f"((d)[2]), "+f"((d)[3]) \
        : "r"((a)[0]), "r"((a)[1]), "r"((a)[2]), "r"((a)[3]), \
          "r"((b)[0]), "r"((b)[1]))

// ---------------- scratch (device globals) ----------------------------------
__device__ __nv_bfloat16 g_hln_h [(size_t)Mtok * Dd];
__device__ __nv_bfloat16 g_hln_l [(size_t)Mtok * Dd];
__device__ __nv_bfloat16 g_act_h [(size_t)Mtok * Ff];
__device__ __nv_bfloat16 g_act_l [(size_t)Mtok * Ff];
__device__ float         g_x2    [(size_t)Mtok * Dd];
__device__ __nv_bfloat16 g_h2_h  [(size_t)Mtok * Dd];
__device__ __nv_bfloat16 g_h2_l  [(size_t)Mtok * Dd];
__device__ float         g_p     [(size_t)Mtok * Dd];
__device__ __nv_bfloat16 g_mx_h  [(size_t)Mtok * Dd];
__device__ __nv_bfloat16 g_mx_l  [(size_t)Mtok * Dd];
__device__ float         g_carry [(size_t)Bn * NCH * Dd];
__device__ __nv_bfloat16 g_w1_h  [(size_t)Ff * Dd];
__device__ __nv_bfloat16 g_w1_l  [(size_t)Ff * Dd];
__device__ __nv_bfloat16 g_w2_h  [(size_t)Dd * Ff];
__device__ __nv_bfloat16 g_w2_l  [(size_t)Dd * Ff];
__device__ __nv_bfloat16 g_pw_h  [(size_t)Dd * Dd];
__device__ __nv_bfloat16 g_pw_l  [(size_t)Dd * Dd];
__device__ __nv_bfloat16 g_ow_h  [(size_t)Dd * Dd];
__device__ __nv_bfloat16 g_ow_l  [(size_t)Dd * Dd];

// ---------------- fp32 -> bf16 hi/lo helpers ---------------------------------
__device__ __forceinline__ void split2(float x0, float x1, uint32_t& hi, uint32_t& lo) {
    __nv_bfloat16 h0 = __float2bfloat16(x0);
    __nv_bfloat16 h1 = __float2bfloat16(x1);
    __nv_bfloat16 l0 = __float2bfloat16(x0 - __bfloat162float(h0));
    __nv_bfloat16 l1 = __float2bfloat16(x1 - __bfloat162float(h1));
    __nv_bfloat162 hh; hh.x = h0; hh.y = h1;
    __nv_bfloat162 ll; ll.x = l0; ll.y = l1;
    hi = *(uint32_t*)&hh; lo = *(uint32_t*)&ll;
}

__global__ void __launch_bounds__(256) conv_hilo(
    const float* __restrict__ src, __nv_bfloat16* __restrict__ hi,
    __nv_bfloat16* __restrict__ lo, int n4)
{
    int i = blockIdx.x * 256 + threadIdx.x;
    if (i >= n4) return;
    float4 v = ((const float4*)src)[i];
    uint2 h, l;
    split2(v.x, v.y, h.x, l.x);
    split2(v.z, v.w, h.y, l.y);
    ((uint2*)hi)[i] = h;
    ((uint2*)lo)[i] = l;
}

// ---------------- LayerNorm -> bf16 hi/lo ------------------------------------
__global__ void __launch_bounds__(256) ln_bf16(
    const float* __restrict__ x, const float* __restrict__ g,
    const float* __restrict__ bet,
    __nv_bfloat16* __restrict__ ohi, __nv_bfloat16* __restrict__ olo)
{
    __shared__ float red[64];
    const long row = blockIdx.x;
    const int  t   = threadIdx.x;

    float4 v = ((const float4*)(x + row * Dd))[t];
    float s = v.x + v.y + v.z + v.w;
    float q = fmaf(v.x, v.x, fmaf(v.y, v.y, fmaf(v.z, v.z, v.w * v.w)));
    #pragma unroll
    for (int o = 16; o > 0; o >>= 1) {
        s += __shfl_xor_sync(0xffffffffu, s, o);
        q += __shfl_xor_sync(0xffffffffu, q, o);
    }
    if ((t & 31) == 0) { red[t >> 5] = s; red[32 + (t >> 5)] = q; }
    __syncthreads();
    if (t < 32) {
        s = (t < 8) ? red[t] : 0.f;
        q = (t < 8) ? red[32 + t] : 0.f;
        #pragma unroll
        for (int o = 4; o > 0; o >>= 1) {
            s += __shfl_xor_sync(0xffffffffu, s, o);
            q += __shfl_xor_sync(0xffffffffu, q, o);
        }
        if (t == 0) { red[0] = s; red[1] = q; }
    }
    __syncthreads();
    const float mean = red[0] * (1.f / Dd);
    const float var  = red[1] * (1.f / Dd) - mean * mean;
    const float rstd = rsqrtf(var + 1e-5f);
    float4 gg = ((const float4*)g)[t];
    float4 bb = ((const float4*)bet)[t];
    float o0 = (v.x - mean) * rstd * gg.x + bb.x;
    float o1 = (v.y - mean) * rstd * gg.y + bb.y;
    float o2 = (v.z - mean) * rstd * gg.z + bb.z;
    float o3 = (v.w - mean) * rstd * gg.w + bb.w;
    uint2 h, l;
    split2(o0, o1, h.x, l.x);
    split2(o2, o3, h.y, l.y);
    ((uint2*)(ohi + row * Dd))[t] = h;
    ((uint2*)(olo + row * Dd))[t] = l;
}

// ---------------- HMMA GEMM: C = (Ahi+Alo)(Whi+Wlo)^T + epilogue ------------
// EPI: 0 = +bias (fp32), 1 = silu(+bias) -> bf16 hi/lo, 2 = +bias+resid (fp32)

// issue one 32KB stage of cp.async loads (A and B tiles, hi+lo)
template<int K>
__device__ __forceinline__ void issue_stage(
    const __nv_bfloat16* __restrict__ aHi, const __nv_bfloat16* __restrict__ aLo,
    const __nv_bfloat16* __restrict__ wHi, const __nv_bfloat16* __restrict__ wLo,
    int kt, uint32_t stagebase, int tid)
{
    const int kofs = kt * BK;
    #pragma unroll
    for (int j = 0; j < 2; j++) {
        const int i = tid + j * 256;          // 0..511
        const int r = i >> 2;                 // row 0..127
        const int c = i & 3;                  // 16B-chunk 0..3
        const int sc = c ^ ((r >> 1) & 3);    // XOR swizzle
        const uint32_t d = stagebase + r * 64 + sc * 16;
        const size_t go = (size_t)r * K + kofs + c * 8;
        CP_ASYNC16(d + OFF_AH, aHi + go);
        CP_ASYNC16(d + OFF_AL, aLo + go);
        CP_ASYNC16(d + OFF_BH, wHi + go);
        CP_ASYNC16(d + OFF_BL, wLo + go);
    }
}

template<int N, int K, int EPI>
__global__ void __launch_bounds__(256, 1) gemm_tc(
    const __nv_bfloat16* __restrict__ Ahi, const __nv_bfloat16* __restrict__ Alo,
    const __nv_bfloat16* __restrict__ Whi, const __nv_bfloat16* __restrict__ Wlo,
    const float* __restrict__ bias, const float* __restrict__ resid,
    float* __restrict__ Cf,
    __nv_bfloat16* __restrict__ Ohi, __nv_bfloat16* __restrict__ Olo)
{
    extern __shared__ char smem[];
    const uint32_t sb = smem_u32(smem);
    const int tid  = threadIdx.x;
    const int wid  = tid >> 5, lane = tid & 31;
    const int m0   = blockIdx.y * BM;
    const int n0   = blockIdx.x * BN;
    const int wm   = (wid & 1) * 64;      // warp M offset within tile
    const int wn   = (wid >> 1) * 32;     // warp N offset within tile

    const __nv_bfloat16* aHi = Ahi + (size_t)m0 * K;
    const __nv_bfloat16* aLo = Alo + (size_t)m0 * K;
    const __nv_bfloat16* wHi = Whi + (size_t)n0 * K;
    const __nv_bfloat16* wLo = Wlo + (size_t)n0 * K;

    constexpr int NK = K / BK;

    // prologue: fill STAGES-1 stages
    #pragma unroll
    for (int s = 0; s < STAGES - 1; s++) {
        issue_stage<K>(aHi, aLo, wHi, wLo, s, sb + s * STAGE_BYTES, tid);
        CP_COMMIT();
    }

    float acc[4][4][4];
    #pragma unroll
    for (int a = 0; a < 4; a++)
        #pragma unroll
        for (int b = 0; b < 4; b++)
            #pragma unroll
            for (int c = 0; c < 4; c++) acc[a][b][c] = 0.f;

    for (int kt = 0; kt < NK; kt++) {
        CP_WAIT2();
        __syncthreads();

        const uint32_t stg = sb + (kt % STAGES) * STAGE_BYTES;
        #pragma unroll
        for (int kc = 0; kc < 2; kc++) {
            uint32_t ah[4][4], al[4][4], bh[4][2], bl[4][2];
            const int halfk = lane >> 4;
            const int chunk = kc * 2 + halfk;
            const int lrow  = lane & 15;
            // A fragments (hi+lo), 4 M-frags of 16 rows
            #pragma unroll
            for (int mf = 0; mf < 4; mf++) {
                const int r = wm + mf * 16 + lrow;
                const int sc = chunk ^ ((r >> 1) & 3);
                const uint32_t ad = stg + r * 64 + sc * 16;
                LDSM_X4(ah[mf][0], ah[mf][1], ah[mf][2], ah[mf][3], ad + OFF_AH);
                LDSM_X4(al[mf][0], al[mf][1], al[mf][2], al[mf][3], ad + OFF_AL);
            }
            // B fragments (hi+lo), 4 N-frags of 8 rows, loaded 16 rows at a time
            #pragma unroll
            for (int p = 0; p < 2; p++) {
                const int r = wn + p * 16 + lrow;
                const int sc = chunk ^ ((r >> 1) & 3);
                const uint32_t bd = stg + r * 64 + sc * 16;
                uint32_t t0, t1, t2, t3;
                LDSM_X4(t0, t1, t2, t3, bd + OFF_BH);
                bh[2 * p][0] = t0; bh[2 * p + 1][0] = t1;
                bh[2 * p][1] = t2; bh[2 * p + 1][1] = t3;
                LDSM_X4(t0, t1, t2, t3, bd + OFF_BL);
                bl[2 * p][0] = t0; bl[2 * p + 1][0] = t1;
                bl[2 * p][1] = t2; bl[2 * p + 1][1] = t3;
            }
            // 3-term split MMAs
            #pragma unroll
            for (int mf = 0; mf < 4; mf++)
                #pragma unroll
                for (int nf = 0; nf < 4; nf++) {
                    MMA_BF16(acc[mf][nf], ah[mf], bh[nf]);
                    MMA_BF16(acc[mf][nf], ah[mf], bl[nf]);
                    MMA_BF16(acc[mf][nf], al[mf], bh[nf]);
                }
        }

        const int nxt = kt + STAGES - 1;
        if (nxt < NK)
            issue_stage<K>(aHi, aLo, wHi, wLo, nxt,
                           sb + (nxt % STAGES) * STAGE_BYTES, tid);
        CP_COMMIT();
    }

    // ---------------- epilogue (register accumulators) ----------------
    #pragma unroll
    for (int nf = 0; nf < 4; nf++) {
        const int col = n0 + wn + nf * 8 + (lane & 3) * 2;
        const float b0 = bias[col], b1 = bias[col + 1];
        #pragma unroll
        for (int mf = 0; mf < 4; mf++) {
            const int r0 = m0 + wm + mf * 16 + (lane >> 2);
            #pragma unroll
            for (int hrow = 0; hrow < 2; hrow++) {
                const size_t row = (size_t)(r0 + hrow * 8);
                float v0 = acc[mf][nf][2 * hrow]     + b0;
                float v1 = acc[mf][nf][2 * hrow + 1] + b1;
                if (EPI == 1) {
                    v0 = v0 / (1.f + __expf(-v0));
                    v1 = v1 / (1.f + __expf(-v1));
                    uint32_t ph, pl;
                    split2(v0, v1, ph, pl);
                    *(uint32_t*)(Ohi + row * N + col) = ph;
                    *(uint32_t*)(Olo + row * N + col) = pl;
                } else {
                    if (EPI == 2) {
                        float2 rr = *(const float2*)(resid + row * N + col);
                        v0 += rr.x; v1 += rr.y;
                    }
                    float2 o = {v0, v1};
                    *(float2*)(Cf + row * N + col) = o;
                }
            }
        }
    }
}

// ---------------- decayed scan (3-pass chunked) ------------------------------
__device__ __forceinline__ float head_decay(const float* dr_ptr, int h) {
    float dr = dr_ptr[h];
    dr = fminf(fmaxf(dr, 0.9f), 1.0f);
    return powf(dr, 0.125f);
}

__global__ void __launch_bounds__(256) scan_pass1(
    const float* __restrict__ p, const float* __restrict__ mix_w,
    const float* __restrict__ decay_raw, float* __restrict__ carry)
{
    const int blk = blockIdx.x;
    const int b = blk / NCH, ch = blk % NCH;
    const int t = threadIdx.x;
    const int s0 = ch * CH;
    float cache[4] = {0.f, 0.f, 0.f, 0.f};
    float dly[4];
    #pragma unroll
    for (int j = 0; j < 4; j++) dly[j] = head_decay(decay_raw, (t + j * 256) >> 7);
    for (int s = s0; s < s0 + CH; s++) {
        const float* pr = p + ((long)b * Sd + s) * Dd;
        #pragma unroll
        for (int j = 0; j < 4; j++) {
            const int f = t + j * 256;
            const int h = f >> 7;
            const float c1 = (h < Hh / 2) ? 1.0f : mix_w[h * Sd + s];
            cache[j] = fmaf(dly[j], cache[j], pr[f] * c1);
        }
    }
    #pragma unroll
    for (int j = 0; j < 4; j++)
        carry[((long)b * NCH + ch) * Dd + t + j * 256] = cache[j];
}

__global__ void __launch_bounds__(256) scan_pass2(
    const float* __restrict__ decay_raw, float* __restrict__ carry)
{
    const int idx = blockIdx.x * 256 + threadIdx.x;
    const int b = idx >> 10, f = idx & 1023;
    const int h = f >> 7;
    float dr = fminf(fmaxf(decay_raw[h], 0.9f), 1.0f);
    float d2 = dr * dr, d4 = d2 * d2;
    const float dC = d4 * d4;   // dr^8 = decay^CH
    float cin = 0.f;
    for (int ch = 0; ch < NCH; ch++) {
        const long i = ((long)b * NCH + ch) * Dd + f;
        const float e = carry[i];
        carry[i] = cin;
        cin = fmaf(dC, cin, e);
    }
}

__global__ void __launch_bounds__(256) scan_pass3(
    const float* __restrict__ p, const float* __restrict__ mix_w,
    const float* __restrict__ mix_b, const float* __restrict__ decay_raw,
    const float* __restrict__ carry,
    __nv_bfloat16* __restrict__ mhi, __nv_bfloat16* __restrict__ mlo)
{
    const int blk = blockIdx.x;
    const int b = blk / NCH, ch = blk % NCH;
    const int t = threadIdx.x;
    const int s0 = ch * CH;
    float cache[4], dly[4];
    #pragma unroll
    for (int j = 0; j < 4; j++) {
        const int f = t + j * 256;
        dly[j]   = head_decay(decay_raw, f >> 7);
        cache[j] = carry[((long)b * NCH + ch) * Dd + f];
    }
    for (int s = s0; s < s0 + CH; s++) {
        const float* pr = p + ((long)b * Sd + s) * Dd;
        const long base = ((long)b * Sd + s) * Dd;
        #pragma unroll
        for (int j = 0; j < 4; j++) {
            const int f = t + j * 256;
            const int h = f >> 7;
            const float mw = mix_w[h * Sd + s];
            const float c1 = (h < Hh / 2) ? 1.0f : mw;
            const float c2 = (h < Hh / 2) ? mw : 1.0f;
            cache[j] = fmaf(dly[j], cache[j], pr[f] * c1);
            const float y = fmaf(c2, cache[j], mix_b[h * Sd + s]);
            __nv_bfloat16 hh = __float2bfloat16(y);
            mhi[base + f] = hh;
            mlo[base + f] = __float2bfloat16(y - __bfloat162float(hh));
        }
    }
}

// ---------------- launcher ----------------------------------------------------
extern "C" void kernel_launch(void* const* d_in, const int* in_sizes, int n_in,
                              void* d_out, int out_size)
{
    const float* x         = (const float*)d_in[0];
    const float* ln1_g     = (const float*)d_in[1];
    const float* ln1_b     = (const float*)d_in[2];
    const float* w1        = (const float*)d_in[3];
    const float* b1        = (const float*)d_in[4];
    const float* w2        = (const float*)d_in[5];
    const float* b2        = (const float*)d_in[6];
    const float* ln2_g     = (const float*)d_in[7];
    const float* ln2_b     = (const float*)d_in[8];
    const float* proj_w    = (const float*)d_in[9];
    const float* proj_b    = (const float*)d_in[10];
    const float* mix_w     = (const float*)d_in[11];
    const float* mix_b     = (const float*)d_in[12];
    const float* decay_raw = (const float*)d_in[13];
    const float* out_w     = (const float*)d_in[14];
    const float* out_b     = (const float*)d_in[15];
    float* out = (float*)d_out;

    __nv_bfloat16 *hlnh, *hlnl, *acth, *actl, *h2h, *h2l, *mxh, *mxl;
    __nv_bfloat16 *w1h, *w1l, *w2h, *w2l, *pwh, *pwl, *owh, *owl;
    float *x2, *pb, *carry;
    cudaGetSymbolAddress((void**)&hlnh, g_hln_h);
    cudaGetSymbolAddress((void**)&hlnl, g_hln_l);
    cudaGetSymbolAddress((void**)&acth, g_act_h);
    cudaGetSymbolAddress((void**)&actl, g_act_l);
    cudaGetSymbolAddress((void**)&x2,   g_x2);
    cudaGetSymbolAddress((void**)&h2h,  g_h2_h);
    cudaGetSymbolAddress((void**)&h2l,  g_h2_l);
    cudaGetSymbolAddress((void**)&pb,   g_p);
    cudaGetSymbolAddress((void**)&mxh,  g_mx_h);
    cudaGetSymbolAddress((void**)&mxl,  g_mx_l);
    cudaGetSymbolAddress((void**)&carry, g_carry);
    cudaGetSymbolAddress((void**)&w1h,  g_w1_h);
    cudaGetSymbolAddress((void**)&w1l,  g_w1_l);
    cudaGetSymbolAddress((void**)&w2h,  g_w2_h);
    cudaGetSymbolAddress((void**)&w2l,  g_w2_l);
    cudaGetSymbolAddress((void**)&pwh,  g_pw_h);
    cudaGetSymbolAddress((void**)&pwl,  g_pw_l);
    cudaGetSymbolAddress((void**)&owh,  g_ow_h);
    cudaGetSymbolAddress((void**)&owl,  g_ow_l);

    cudaFuncSetAttribute((const void*)gemm_tc<Ff, Dd, 1>,
                         cudaFuncAttributeMaxDynamicSharedMemorySize, GEMM_SMEM);
    cudaFuncSetAttribute((const void*)gemm_tc<Dd, Ff, 2>,
                         cudaFuncAttributeMaxDynamicSharedMemorySize, GEMM_SMEM);
    cudaFuncSetAttribute((const void*)gemm_tc<Dd, Dd, 0>,
                         cudaFuncAttributeMaxDynamicSharedMemorySize, GEMM_SMEM);
    cudaFuncSetAttribute((const void*)gemm_tc<Dd, Dd, 2>,
                         cudaFuncAttributeMaxDynamicSharedMemorySize, GEMM_SMEM);

    // 0) weight conversions fp32 -> bf16 hi/lo
    conv_hilo<<<(Ff * Dd / 4 + 255) / 256, 256>>>(w1, w1h, w1l, Ff * Dd / 4);
    conv_hilo<<<(Dd * Ff / 4 + 255) / 256, 256>>>(w2, w2h, w2l, Dd * Ff / 4);
    conv_hilo<<<(Dd * Dd / 4 + 255) / 256, 256>>>(proj_w, pwh, pwl, Dd * Dd / 4);
    conv_hilo<<<(Dd * Dd / 4 + 255) / 256, 256>>>(out_w, owh, owl, Dd * Dd / 4);

    // 1) LN1 -> bf16 hi/lo
    ln_bf16<<<Mtok, 256>>>(x, ln1_g, ln1_b, hlnh, hlnl);
    // 2) act = silu(hln @ w1^T + b1) -> bf16 hi/lo       [16384, 4096]
    gemm_tc<Ff, Dd, 1><<<dim3(Ff / BN, Mtok / BM), 256, GEMM_SMEM>>>(
        hlnh, hlnl, w1h, w1l, b1, nullptr, nullptr, acth, actl);
    // 3) x2 = act @ w2^T + b2 + x (fp32)                 [16384, 1024]
    gemm_tc<Dd, Ff, 2><<<dim3(Dd / BN, Mtok / BM), 256, GEMM_SMEM>>>(
        acth, actl, w2h, w2l, b2, x, x2, nullptr, nullptr);
    // 4) LN2 -> bf16 hi/lo
    ln_bf16<<<Mtok, 256>>>(x2, ln2_g, ln2_b, h2h, h2l);
    // 5) p = h2 @ proj_w^T + proj_b (fp32)               [16384, 1024]
    gemm_tc<Dd, Dd, 0><<<dim3(Dd / BN, Mtok / BM), 256, GEMM_SMEM>>>(
        h2h, h2l, pwh, pwl, proj_b, nullptr, pb, nullptr, nullptr);
    // 6-8) decayed scan over S (mixed -> bf16 hi/lo)
    scan_pass1<<<Bn * NCH, 256>>>(pb, mix_w, decay_raw, carry);
    scan_pass2<<<(Bn * Dd) / 256, 256>>>(decay_raw, carry);
    scan_pass3<<<Bn * NCH, 256>>>(pb, mix_w, mix_b, decay_raw, carry, mxh, mxl);
    // 9) out = mixed @ out_w^T + out_b + x2 (fp32)       [16384, 1024]
    gemm_tc<Dd, Dd, 2><<<dim3(Dd / BN, Mtok / BM), 256, GEMM_SMEM>>>(
        mxh, mxl, owh, owl, out_b, x2, out, nullptr, nullptr);
}

// round 4
// speedup vs baseline: 2.4588x; 1.0917x over previous
#include <cuda_runtime.h>
#include <cuda_bf16.h>
#include <math.h>
#include <stdint.h>

// ---------------- problem constants ----------------
#define Bn   4
#define Sd   4096
#define Dd   1024
#define Hh   8
#define Ff   4096          // EXP * D
#define Mtok 16384         // B * S
#define NCH  64            // scan chunks
#define CH   (Sd / NCH)    // 64 steps per chunk

// GEMM tiling
#define BM 128
#define BN 128
#define BK 32
#define STAGES 3
#define STAGE_BYTES 32768          // Ah 8K | Al 8K | Bh 8K | Bl 8K
#define OFF_AH 0
#define OFF_AL 8192
#define OFF_BH 16384
#define OFF_BL 24576
#define GEMM_SMEM (STAGES * STAGE_BYTES)

// ---------------- small PTX helpers ------------------------------------------
__device__ __forceinline__ uint32_t smem_u32(const void* p) {
    uint32_t a;
    asm("{ .reg .u64 t; cvta.to.shared.u64 t, %1; cvt.u32.u64 %0, t; }"
        : "=r"(a) : "l"(p));
    return a;
}
#define CP_ASYNC16(dst, src) \
    asm volatile("cp.async.cg.shared.global [%0], [%1], 16;" \
        :: "r"(dst), "l"(src) : "memory")
#define CP_COMMIT() asm volatile("cp.async.commit_group;" ::: "memory")
#define CP_WAIT1()  asm volatile("cp.async.wait_group 1;" ::: "memory")

#define LDSM_X4(r0, r1, r2, r3, addr) \
    asm volatile("ldmatrix.sync.aligned.m8n8.x4.shared.b16 {%0,%1,%2,%3}, [%4];" \
        : "=r"(r0), "=r"(r1), "=r"(r2), "=r"(r3) : "r"(addr))

#define MMA_BF16(d, a, b) \
    asm volatile("mma.sync.aligned.m16n8k16.row.col.f32.bf16.bf16.f32 " \
        "{%0,%1,%2,%3}, {%4,%5,%6,%7}, {%8,%9}, {%0,%1,%2,%3};" \
        : "+f"((d)[0]), "+f"((d)[1]), "+f"((d)[2]), "+f"((d)[3]) \
        : "r"((a)[0]), "r"((a)[1]), "r"((a)[2]), "r"((a)[3]), \
          "r"((b)[0]), "r"((b)[1]))

// ---------------- scratch (device globals) ----------------------------------
__device__ __nv_bfloat16 g_hln_h [(size_t)Mtok * Dd];
__device__ __nv_bfloat16 g_hln_l [(size_t)Mtok * Dd];
__device__ __nv_bfloat16 g_act_h [(size_t)Mtok * Ff];
__device__ __nv_bfloat16 g_act_l [(size_t)Mtok * Ff];
__device__ float         g_x2    [(size_t)Mtok * Dd];
__device__ __nv_bfloat16 g_h2_h  [(size_t)Mtok * Dd];
__device__ __nv_bfloat16 g_h2_l  [(size_t)Mtok * Dd];
__device__ float         g_p     [(size_t)Mtok * Dd];
__device__ __nv_bfloat16 g_mx_h  [(size_t)Mtok * Dd];
__device__ __nv_bfloat16 g_mx_l  [(size_t)Mtok * Dd];
__device__ float         g_carry [(size_t)Bn * NCH * Dd];
__device__ __nv_bfloat16 g_w1_h  [(size_t)Ff * Dd];
__device__ __nv_bfloat16 g_w1_l  [(size_t)Ff * Dd];
__device__ __nv_bfloat16 g_w2_h  [(size_t)Dd * Ff];
__device__ __nv_bfloat16 g_w2_l  [(size_t)Dd * Ff];
__device__ __nv_bfloat16 g_pw_h  [(size_t)Dd * Dd];
__device__ __nv_bfloat16 g_pw_l  [(size_t)Dd * Dd];
__device__ __nv_bfloat16 g_ow_h  [(size_t)Dd * Dd];
__device__ __nv_bfloat16 g_ow_l  [(size_t)Dd * Dd];

// ---------------- fp32 -> bf16 hi/lo helpers ---------------------------------
__device__ __forceinline__ void split2(float x0, float x1, uint32_t& hi, uint32_t& lo) {
    __nv_bfloat16 h0 = __float2bfloat16(x0);
    __nv_bfloat16 h1 = __float2bfloat16(x1);
    __nv_bfloat16 l0 = __float2bfloat16(x0 - __bfloat162float(h0));
    __nv_bfloat16 l1 = __float2bfloat16(x1 - __bfloat162float(h1));
    __nv_bfloat162 hh; hh.x = h0; hh.y = h1;
    __nv_bfloat162 ll; ll.x = l0; ll.y = l1;
    hi = *(uint32_t*)&hh; lo = *(uint32_t*)&ll;
}

__global__ void __launch_bounds__(256) conv_hilo(
    const float* __restrict__ src, __nv_bfloat16* __restrict__ hi,
    __nv_bfloat16* __restrict__ lo, int n4)
{
    int i = blockIdx.x * 256 + threadIdx.x;
    if (i >= n4) return;
    float4 v = ((const float4*)src)[i];
    uint2 h, l;
    split2(v.x, v.y, h.x, l.x);
    split2(v.z, v.w, h.y, l.y);
    ((uint2*)hi)[i] = h;
    ((uint2*)lo)[i] = l;
}

// ---------------- LayerNorm -> bf16 hi/lo ------------------------------------
__global__ void __launch_bounds__(256) ln_bf16(
    const float* __restrict__ x, const float* __restrict__ g,
    const float* __restrict__ bet,
    __nv_bfloat16* __restrict__ ohi, __nv_bfloat16* __restrict__ olo)
{
    __shared__ float red[64];
    const long row = blockIdx.x;
    const int  t   = threadIdx.x;

    float4 v = ((const float4*)(x + row * Dd))[t];
    float s = v.x + v.y + v.z + v.w;
    float q = fmaf(v.x, v.x, fmaf(v.y, v.y, fmaf(v.z, v.z, v.w * v.w)));
    #pragma unroll
    for (int o = 16; o > 0; o >>= 1) {
        s += __shfl_xor_sync(0xffffffffu, s, o);
        q += __shfl_xor_sync(0xffffffffu, q, o);
    }
    if ((t & 31) == 0) { red[t >> 5] = s; red[32 + (t >> 5)] = q; }
    __syncthreads();
    if (t < 32) {
        s = (t < 8) ? red[t] : 0.f;
        q = (t < 8) ? red[32 + t] : 0.f;
        #pragma unroll
        for (int o = 4; o > 0; o >>= 1) {
            s += __shfl_xor_sync(0xffffffffu, s, o);
            q += __shfl_xor_sync(0xffffffffu, q, o);
        }
        if (t == 0) { red[0] = s; red[1] = q; }
    }
    __syncthreads();
    const float mean = red[0] * (1.f / Dd);
    const float var  = red[1] * (1.f / Dd) - mean * mean;
    const float rstd = rsqrtf(var + 1e-5f);
    float4 gg = ((const float4*)g)[t];
    float4 bb = ((const float4*)bet)[t];
    float o0 = (v.x - mean) * rstd * gg.x + bb.x;
    float o1 = (v.y - mean) * rstd * gg.y + bb.y;
    float o2 = (v.z - mean) * rstd * gg.z + bb.z;
    float o3 = (v.w - mean) * rstd * gg.w + bb.w;
    uint2 h, l;
    split2(o0, o1, h.x, l.x);
    split2(o2, o3, h.y, l.y);
    ((uint2*)(ohi + row * Dd))[t] = h;
    ((uint2*)(olo + row * Dd))[t] = l;
}

// ---------------- HMMA GEMM: C = (Ahi+Alo)(Whi+Wlo)^T + epilogue ------------
// EPI: 0 = +bias (fp32), 1 = silu(+bias) -> bf16 hi/lo, 2 = +bias+resid (fp32)

template<int K>
__device__ __forceinline__ void issue_stage(
    const __nv_bfloat16* __restrict__ aHi, const __nv_bfloat16* __restrict__ aLo,
    const __nv_bfloat16* __restrict__ wHi, const __nv_bfloat16* __restrict__ wLo,
    int kt, uint32_t stagebase, int tid)
{
    const int kofs = kt * BK;
    #pragma unroll
    for (int j = 0; j < 2; j++) {
        const int i = tid + j * 256;          // 0..511
        const int r = i >> 2;                 // row 0..127
        const int c = i & 3;                  // 16B-chunk 0..3
        const int sc = c ^ ((r >> 1) & 3);    // XOR swizzle
        const uint32_t d = stagebase + r * 64 + sc * 16;
        const size_t go = (size_t)r * K + kofs + c * 8;
        CP_ASYNC16(d + OFF_AH, aHi + go);
        CP_ASYNC16(d + OFF_AL, aLo + go);
        CP_ASYNC16(d + OFF_BH, wHi + go);
        CP_ASYNC16(d + OFF_BL, wLo + go);
    }
}

template<int N, int K, int EPI>
__global__ void __launch_bounds__(256, 2) gemm_tc(
    const __nv_bfloat16* __restrict__ Ahi, const __nv_bfloat16* __restrict__ Alo,
    const __nv_bfloat16* __restrict__ Whi, const __nv_bfloat16* __restrict__ Wlo,
    const float* __restrict__ bias, const float* __restrict__ resid,
    float* __restrict__ Cf,
    __nv_bfloat16* __restrict__ Ohi, __nv_bfloat16* __restrict__ Olo)
{
    extern __shared__ char smem[];
    const uint32_t sb = smem_u32(smem);
    const int tid  = threadIdx.x;
    const int wid  = tid >> 5, lane = tid & 31;
    const int m0   = blockIdx.y * BM;
    const int n0   = blockIdx.x * BN;
    const int wm   = (wid & 1) * 64;      // warp M offset within tile
    const int wn   = (wid >> 1) * 32;     // warp N offset within tile

    const __nv_bfloat16* aHi = Ahi + (size_t)m0 * K;
    const __nv_bfloat16* aLo = Alo + (size_t)m0 * K;
    const __nv_bfloat16* wHi = Whi + (size_t)n0 * K;
    const __nv_bfloat16* wLo = Wlo + (size_t)n0 * K;

    constexpr int NK = K / BK;

    // prologue: fill STAGES-1 stages
    #pragma unroll
    for (int s = 0; s < STAGES - 1; s++) {
        issue_stage<K>(aHi, aLo, wHi, wLo, s, sb + s * STAGE_BYTES, tid);
        CP_COMMIT();
    }

    float acc[4][4][4];
    #pragma unroll
    for (int a = 0; a < 4; a++)
        #pragma unroll
        for (int b = 0; b < 4; b++)
            #pragma unroll
            for (int c = 0; c < 4; c++) acc[a][b][c] = 0.f;

    for (int kt = 0; kt < NK; kt++) {
        CP_WAIT1();
        __syncthreads();

        // issue next stage FIRST so loads overlap the MMAs below
        const int nxt = kt + STAGES - 1;
        if (nxt < NK)
            issue_stage<K>(aHi, aLo, wHi, wLo, nxt,
                           sb + (nxt % STAGES) * STAGE_BYTES, tid);
        CP_COMMIT();

        const uint32_t stg = sb + (kt % STAGES) * STAGE_BYTES;
        #pragma unroll
        for (int kc = 0; kc < 2; kc++) {
            const int halfk = lane >> 4;
            const int chunk = kc * 2 + halfk;
            const int lrow  = lane & 15;
            // A fragments (hi+lo), 4 M-frags of 16 rows
            uint32_t ah[4][4], al[4][4];
            #pragma unroll
            for (int mf = 0; mf < 4; mf++) {
                const int r = wm + mf * 16 + lrow;
                const int sc = chunk ^ ((r >> 1) & 3);
                const uint32_t ad = stg + r * 64 + sc * 16;
                LDSM_X4(ah[mf][0], ah[mf][1], ah[mf][2], ah[mf][3], ad + OFF_AH);
                LDSM_X4(al[mf][0], al[mf][1], al[mf][2], al[mf][3], ad + OFF_AL);
            }
            // B fragments loaded per 16-row pair to keep register pressure low
            #pragma unroll
            for (int p = 0; p < 2; p++) {
                const int r = wn + p * 16 + lrow;
                const int sc = chunk ^ ((r >> 1) & 3);
                const uint32_t bd = stg + r * 64 + sc * 16;
                uint32_t bh[2][2], bl[2][2];
                uint32_t t0, t1, t2, t3;
                LDSM_X4(t0, t1, t2, t3, bd + OFF_BH);
                bh[0][0] = t0; bh[1][0] = t1; bh[0][1] = t2; bh[1][1] = t3;
                LDSM_X4(t0, t1, t2, t3, bd + OFF_BL);
                bl[0][0] = t0; bl[1][0] = t1; bl[0][1] = t2; bl[1][1] = t3;
                #pragma unroll
                for (int mf = 0; mf < 4; mf++)
                    #pragma unroll
                    for (int q = 0; q < 2; q++) {
                        float* d = acc[mf][2 * p + q];
                        MMA_BF16(d, ah[mf], bh[q]);
                        MMA_BF16(d, ah[mf], bl[q]);
                        MMA_BF16(d, al[mf], bh[q]);
                    }
            }
        }
    }

    // ---------------- epilogue (register accumulators) ----------------
    #pragma unroll
    for (int nf = 0; nf < 4; nf++) {
        const int col = n0 + wn + nf * 8 + (lane & 3) * 2;
        const float b0 = bias[col], b1 = bias[col + 1];
        #pragma unroll
        for (int mf = 0; mf < 4; mf++) {
            const int r0 = m0 + wm + mf * 16 + (lane >> 2);
            #pragma unroll
            for (int hrow = 0; hrow < 2; hrow++) {
                const size_t row = (size_t)(r0 + hrow * 8);
                float v0 = acc[mf][nf][2 * hrow]     + b0;
                float v1 = acc[mf][nf][2 * hrow + 1] + b1;
                if (EPI == 1) {
                    v0 = v0 / (1.f + __expf(-v0));
                    v1 = v1 / (1.f + __expf(-v1));
                    uint32_t ph, pl;
                    split2(v0, v1, ph, pl);
                    *(uint32_t*)(Ohi + row * N + col) = ph;
                    *(uint32_t*)(Olo + row * N + col) = pl;
                } else {
                    if (EPI == 2) {
                        float2 rr = *(const float2*)(resid + row * N + col);
                        v0 += rr.x; v1 += rr.y;
                    }
                    float2 o = {v0, v1};
                    *(float2*)(Cf + row * N + col) = o;
                }
            }
        }
    }
}

// ---------------- decayed scan (3-pass chunked) ------------------------------
__device__ __forceinline__ float head_decay(const float* dr_ptr, int h) {
    float dr = dr_ptr[h];
    dr = fminf(fmaxf(dr, 0.9f), 1.0f);
    return powf(dr, 0.125f);
}

__global__ void __launch_bounds__(256) scan_pass1(
    const float* __restrict__ p, const float* __restrict__ mix_w,
    const float* __restrict__ decay_raw, float* __restrict__ carry)
{
    const int blk = blockIdx.x;
    const int b = blk / NCH, ch = blk % NCH;
    const int t = threadIdx.x;
    const int s0 = ch * CH;
    float cache[4] = {0.f, 0.f, 0.f, 0.f};
    float dly[4];
    #pragma unroll
    for (int j = 0; j < 4; j++) dly[j] = head_decay(decay_raw, (t + j * 256) >> 7);
    for (int s = s0; s < s0 + CH; s++) {
        const float* pr = p + ((long)b * Sd + s) * Dd;
        #pragma unroll
        for (int j = 0; j < 4; j++) {
            const int f = t + j * 256;
            const int h = f >> 7;
            const float c1 = (h < Hh / 2) ? 1.0f : mix_w[h * Sd + s];
            cache[j] = fmaf(dly[j], cache[j], pr[f] * c1);
        }
    }
    #pragma unroll
    for (int j = 0; j < 4; j++)
        carry[((long)b * NCH + ch) * Dd + t + j * 256] = cache[j];
}

__global__ void __launch_bounds__(256) scan_pass2(
    const float* __restrict__ decay_raw, float* __restrict__ carry)
{
    const int idx = blockIdx.x * 256 + threadIdx.x;
    const int b = idx >> 10, f = idx & 1023;
    const int h = f >> 7;
    float dr = fminf(fmaxf(decay_raw[h], 0.9f), 1.0f);
    float d2 = dr * dr, d4 = d2 * d2;
    const float dC = d4 * d4;   // dr^8 = decay^CH
    float cin = 0.f;
    for (int ch = 0; ch < NCH; ch++) {
        const long i = ((long)b * NCH + ch) * Dd + f;
        const float e = carry[i];
        carry[i] = cin;
        cin = fmaf(dC, cin, e);
    }
}

__global__ void __launch_bounds__(256) scan_pass3(
    const float* __restrict__ p, const float* __restrict__ mix_w,
    const float* __restrict__ mix_b, const float* __restrict__ decay_raw,
    const float* __restrict__ carry,
    __nv_bfloat16* __restrict__ mhi, __nv_bfloat16* __restrict__ mlo)
{
    const int blk = blockIdx.x;
    const int b = blk / NCH, ch = blk % NCH;
    const int t = threadIdx.x;
    const int s0 = ch * CH;
    float cache[4], dly[4];
    #pragma unroll
    for (int j = 0; j < 4; j++) {
        const int f = t + j * 256;
        dly[j]   = head_decay(decay_raw, f >> 7);
        cache[j] = carry[((long)b * NCH + ch) * Dd + f];
    }
    for (int s = s0; s < s0 + CH; s++) {
        const float* pr = p + ((long)b * Sd + s) * Dd;
        const long base = ((long)b * Sd + s) * Dd;
        #pragma unroll
        for (int j = 0; j < 4; j++) {
            const int f = t + j * 256;
            const int h = f >> 7;
            const float mw = mix_w[h * Sd + s];
            const float c1 = (h < Hh / 2) ? 1.0f : mw;
            const float c2 = (h < Hh / 2) ? mw : 1.0f;
            cache[j] = fmaf(dly[j], cache[j], pr[f] * c1);
            const float y = fmaf(c2, cache[j], mix_b[h * Sd + s]);
            __nv_bfloat16 hh = __float2bfloat16(y);
            mhi[base + f] = hh;
            mlo[base + f] = __float2bfloat16(y - __bfloat162float(hh));
        }
    }
}

// ---------------- launcher ----------------------------------------------------
extern "C" void kernel_launch(void* const* d_in, const int* in_sizes, int n_in,
                              void* d_out, int out_size)
{
    const float* x         = (const float*)d_in[0];
    const float* ln1_g     = (const float*)d_in[1];
    const float* ln1_b     = (const float*)d_in[2];
    const float* w1        = (const float*)d_in[3];
    const float* b1        = (const float*)d_in[4];
    const float* w2        = (const float*)d_in[5];
    const float* b2        = (const float*)d_in[6];
    const float* ln2_g     = (const float*)d_in[7];
    const float* ln2_b     = (const float*)d_in[8];
    const float* proj_w    = (const float*)d_in[9];
    const float* proj_b    = (const float*)d_in[10];
    const float* mix_w     = (const float*)d_in[11];
    const float* mix_b     = (const float*)d_in[12];
    const float* decay_raw = (const float*)d_in[13];
    const float* out_w     = (const float*)d_in[14];
    const float* out_b     = (const float*)d_in[15];
    float* out = (float*)d_out;

    __nv_bfloat16 *hlnh, *hlnl, *acth, *actl, *h2h, *h2l, *mxh, *mxl;
    __nv_bfloat16 *w1h, *w1l, *w2h, *w2l, *pwh, *pwl, *owh, *owl;
    float *x2, *pb, *carry;
    cudaGetSymbolAddress((void**)&hlnh, g_hln_h);
    cudaGetSymbolAddress((void**)&hlnl, g_hln_l);
    cudaGetSymbolAddress((void**)&acth, g_act_h);
    cudaGetSymbolAddress((void**)&actl, g_act_l);
    cudaGetSymbolAddress((void**)&x2,   g_x2);
    cudaGetSymbolAddress((void**)&h2h,  g_h2_h);
    cudaGetSymbolAddress((void**)&h2l,  g_h2_l);
    cudaGetSymbolAddress((void**)&pb,   g_p);
    cudaGetSymbolAddress((void**)&mxh,  g_mx_h);
    cudaGetSymbolAddress((void**)&mxl,  g_mx_l);
    cudaGetSymbolAddress((void**)&carry, g_carry);
    cudaGetSymbolAddress((void**)&w1h,  g_w1_h);
    cudaGetSymbolAddress((void**)&w1l,  g_w1_l);
    cudaGetSymbolAddress((void**)&w2h,  g_w2_h);
    cudaGetSymbolAddress((void**)&w2l,  g_w2_l);
    cudaGetSymbolAddress((void**)&pwh,  g_pw_h);
    cudaGetSymbolAddress((void**)&pwl,  g_pw_l);
    cudaGetSymbolAddress((void**)&owh,  g_ow_h);
    cudaGetSymbolAddress((void**)&owl,  g_ow_l);

    cudaFuncSetAttribute((const void*)gemm_tc<Ff, Dd, 1>,
                         cudaFuncAttributeMaxDynamicSharedMemorySize, GEMM_SMEM);
    cudaFuncSetAttribute((const void*)gemm_tc<Dd, Ff, 2>,
                         cudaFuncAttributeMaxDynamicSharedMemorySize, GEMM_SMEM);
    cudaFuncSetAttribute((const void*)gemm_tc<Dd, Dd, 0>,
                         cudaFuncAttributeMaxDynamicSharedMemorySize, GEMM_SMEM);
    cudaFuncSetAttribute((const void*)gemm_tc<Dd, Dd, 2>,
                         cudaFuncAttributeMaxDynamicSharedMemorySize, GEMM_SMEM);

    // 0) weight conversions fp32 -> bf16 hi/lo
    conv_hilo<<<(Ff * Dd / 4 + 255) / 256, 256>>>(w1, w1h, w1l, Ff * Dd / 4);
    conv_hilo<<<(Dd * Ff / 4 + 255) / 256, 256>>>(w2, w2h, w2l, Dd * Ff / 4);
    conv_hilo<<<(Dd * Dd / 4 + 255) / 256, 256>>>(proj_w, pwh, pwl, Dd * Dd / 4);
    conv_hilo<<<(Dd * Dd / 4 + 255) / 256, 256>>>(out_w, owh, owl, Dd * Dd / 4);

    // 1) LN1 -> bf16 hi/lo
    ln_bf16<<<Mtok, 256>>>(x, ln1_g, ln1_b, hlnh, hlnl);
    // 2) act = silu(hln @ w1^T + b1) -> bf16 hi/lo       [16384, 4096]
    gemm_tc<Ff, Dd, 1><<<dim3(Ff / BN, Mtok / BM), 256, GEMM_SMEM>>>(
        hlnh, hlnl, w1h, w1l, b1, nullptr, nullptr, acth, actl);
    // 3) x2 = act @ w2^T + b2 + x (fp32)                 [16384, 1024]
    gemm_tc<Dd, Ff, 2><<<dim3(Dd / BN, Mtok / BM), 256, GEMM_SMEM>>>(
        acth, actl, w2h, w2l, b2, x, x2, nullptr, nullptr);
    // 4) LN2 -> bf16 hi/lo
    ln_bf16<<<Mtok, 256>>>(x2, ln2_g, ln2_b, h2h, h2l);
    // 5) p = h2 @ proj_w^T + proj_b (fp32)               [16384, 1024]
    gemm_tc<Dd, Dd, 0><<<dim3(Dd / BN, Mtok / BM), 256, GEMM_SMEM>>>(
        h2h, h2l, pwh, pwl, proj_b, nullptr, pb, nullptr, nullptr);
    // 6-8) decayed scan over S (mixed -> bf16 hi/lo)
    scan_pass1<<<Bn * NCH, 256>>>(pb, mix_w, decay_raw, carry);
    scan_pass2<<<(Bn * Dd) / 256, 256>>>(decay_raw, carry);
    scan_pass3<<<Bn * NCH, 256>>>(pb, mix_w, mix_b, decay_raw, carry, mxh, mxl);
    // 9) out = mixed @ out_w^T + out_b + x2 (fp32)       [16384, 1024]
    gemm_tc<Dd, Dd, 2><<<dim3(Dd / BN, Mtok / BM), 256, GEMM_SMEM>>>(
        mxh, mxl, owh, owl, out_b, x2, out, nullptr, nullptr);
}